// round 3
// baseline (speedup 1.0000x reference)
#include <cuda_runtime.h>
#include <math.h>

typedef unsigned long long u64;

// ---------------- problem constants ----------------
#define NB     2
#define CINC   8
#define COUTC  8
#define NLAT   128
#define NLON   256
#define EMB    256
#define HID    512
#define NLAY   4
#define MM     129
#define MP     132                      // padded mmax (multiple of 4)
#define MI     264                      // interleaved spectral width = 2*MP
#define PSP    (NLAT*NLON)              // 32768
#define ROWS   (NB*EMB*NLAT)            // 65536

// ---------------- scratch ----------------
__device__ float2 g_A[(size_t)ROWS*MP];            // spectral buf A  [row][m132] interleaved
__device__ float2 g_B[(size_t)ROWS*MP];            // spectral buf B
__device__ float  g_h [(size_t)NB*EMB*PSP];
__device__ float  g_t [(size_t)NB*HID*PSP];
__device__ float  g_wtT[(size_t)MP*NLAT*NLAT];     // sht_wt  -> [m][k][l], zero-padded m
__device__ float  g_iwt[(size_t)MP*NLAT*NLAT];     // isht_wt -> [m][l][k], zero-padded m
__device__ float2 g_w[(size_t)NLAY*NLAT*EMB*EMB];  // spec_w  -> [lay][l][i][o] complex
__device__ float  g_Tf[(size_t)NLON*MI + 256];     // fwd DFT table [n][mi], row stride MI
__device__ float  g_Ti[(size_t)MI*NLON + 256];     // inv DFT table [mi][n]

// ---------------- f32x2 helpers ----------------
__device__ __forceinline__ u64 pk2(float lo, float hi){
    u64 r; asm("mov.b64 %0,{%1,%2};" : "=l"(r) : "f"(lo), "f"(hi)); return r;
}
__device__ __forceinline__ u64 dup2f(float v){ return pk2(v, v); }
__device__ __forceinline__ void fma2(u64 &d, u64 a, u64 b){
    asm("fma.rn.f32x2 %0,%1,%2,%0;" : "+l"(d) : "l"(a), "l"(b));
}
__device__ __forceinline__ float2 up2(u64 v){
    float x, y; asm("mov.b64 {%0,%1},%2;" : "=f"(x), "=f"(y) : "l"(v));
    return make_float2(x, y);
}
__device__ __forceinline__ float gelu_tanh(float x){
    float x3 = x*x*x;
    return 0.5f*x*(1.0f + tanhf(0.79788456080286535588f*(x + 0.044715f*x3)));
}

// ---------------- tables ----------------
__global__ void k_init_tables(){
    int i = blockIdx.x*blockDim.x + threadIdx.x;
    if (i >= NLON*MI) return;
    const double PI_D = 3.141592653589793238462643383279502884;
    {   // forward: Tf[n][mi], mi = 2m+c;  value = (2pi/256) * e^{-i 2pi n m /256}
        int n = i / MI, mi = i % MI, m = mi >> 1, c = mi & 1;
        float v = 0.f;
        if (m < MM){
            double ang = -2.0*PI_D*(double)((n*m)&255)/256.0;
            double sc  =  2.0*PI_D/256.0;
            v = (float)((c ? sin(ang) : cos(ang))*sc);
        }
        g_Tf[i] = v;
    }
    {   // inverse: Ti[mi][n]
        int mi = i / NLON, n = i % NLON, m = mi >> 1, c = mi & 1;
        float v = 0.f;
        if (m < MM){
            double a2 = 2.0*PI_D*(double)((n*m)&255)/256.0;
            if (m==0 || m==128) v = c ? 0.f : (float)cos(a2);
            else                v = c ? (float)(-2.0*sin(a2)) : (float)(2.0*cos(a2));
        }
        g_Ti[i] = v;
    }
}

// sht_wt[m][l][k] -> g_wtT[m][k][l] ; isht_wt[m][l][k] -> g_iwt[m][l][k]; pad m to 132 w/ zeros
__global__ void k_prep_wt(const float* __restrict__ sht, const float* __restrict__ isht){
    int i = blockIdx.x*blockDim.x + threadIdx.x;
    if (i >= MP*NLAT*NLAT) return;
    int t = i & 127;
    int j = (i >> 7) & 127;
    int m = i >> 14;
    float v1 = 0.f, v2 = 0.f;
    if (m < MM){
        v1 = sht [((size_t)m*NLAT + t)*NLAT + j];   // out[m][k=j][l=t]
        v2 = isht[((size_t)m*NLAT + j)*NLAT + t];   // out[m][l=j][k=t]
    }
    g_wtT[i] = v1;
    g_iwt[i] = v2;
}

// spec_w [lay][i][o][l]{re,im} -> g_w [lay][l][i][o] float2 (smem-tiled transpose)
__global__ __launch_bounds__(256) void k_pack_w(const float2* __restrict__ sw){
    __shared__ float2 tile[32][33];
    int li = blockIdx.x;                 // lay*256 + i
    int o0 = blockIdx.y*32, l0 = blockIdx.z*32;
    int oo = threadIdx.x >> 5, ll = threadIdx.x & 31;
    #pragma unroll
    for (int p=0;p<4;p++){
        int o = oo + p*8;
        tile[o][ll] = sw[((size_t)li*EMB + o0 + o)*NLAT + l0 + ll];
    }
    __syncthreads();
    int lay = li >> 8, ii = li & 255;
    #pragma unroll
    for (int p=0;p<4;p++){
        int l = oo + p*8;
        g_w[(((size_t)lay*NLAT + l0 + l)*EMB + ii)*EMB + o0 + ll] = tile[ll][l];
    }
}

// ---------------- SGEMM: C[b,m,n] = sum_k A[m,k]*B[b,k,n]  (128x128, FFMA2, dbuf) ------
// flags: 1 = gelu, 2 = add addp[b,m,n], 4 = add addp[m,n], 8 = no bias
__global__ __launch_bounds__(256) void k_sgemm(
    const float* __restrict__ A, const float* __restrict__ Bmat,
    float* C, const float* __restrict__ bias, const float* __restrict__ addp,
    int M, int N, int K, int flags)
{
    __shared__ u64   Asd[2][8][128];
    __shared__ float Bs [2][8][128];
    int b = blockIdx.z;
    const float* Bp = Bmat + (size_t)b*K*N;
    float* Cp       = C    + (size_t)b*M*N;
    int m0 = blockIdx.y*128, n0 = blockIdx.x*128;
    int tid = threadIdx.x, tx = tid & 15, ty = tid >> 4;
    int ar = tid >> 1,  ac = (tid & 1)*4;
    int br = tid >> 5,  bc = (tid & 31)*4;

    // preload tile 0
    float4 av = make_float4(0.f,0.f,0.f,0.f);
    if (m0+ar < M) av = *(const float4*)&A[(size_t)(m0+ar)*K + ac];
    float4 bv = *(const float4*)&Bp[(size_t)br*N + n0 + bc];
    Asd[0][ac+0][ar]=dup2f(av.x); Asd[0][ac+1][ar]=dup2f(av.y);
    Asd[0][ac+2][ar]=dup2f(av.z); Asd[0][ac+3][ar]=dup2f(av.w);
    *(float4*)&Bs[0][br][bc] = bv;
    __syncthreads();

    u64 acc[8][4];
    #pragma unroll
    for (int i=0;i<8;i++)
        #pragma unroll
        for (int j=0;j<4;j++) acc[i][j]=0ull;

    int p = 0;
    for (int k0=0;k0<K;k0+=8){
        int k1 = k0 + 8;
        bool more = (k1 < K);
        if (more){
            av = make_float4(0.f,0.f,0.f,0.f);
            if (m0+ar < M) av = *(const float4*)&A[(size_t)(m0+ar)*K + k1 + ac];
            bv = *(const float4*)&Bp[(size_t)(k1+br)*N + n0 + bc];
        }
        #pragma unroll
        for (int kk=0;kk<8;kk++){
            ulonglong2 a01 = *(ulonglong2*)&Asd[p][kk][ty*8+0];
            ulonglong2 a23 = *(ulonglong2*)&Asd[p][kk][ty*8+2];
            ulonglong2 a45 = *(ulonglong2*)&Asd[p][kk][ty*8+4];
            ulonglong2 a67 = *(ulonglong2*)&Asd[p][kk][ty*8+6];
            float4 b03 = *(float4*)&Bs[p][kk][tx*8];
            float4 b47 = *(float4*)&Bs[p][kk][tx*8+4];
            u64 bb[4] = {pk2(b03.x,b03.y), pk2(b03.z,b03.w),
                         pk2(b47.x,b47.y), pk2(b47.z,b47.w)};
            u64 ad[8] = {a01.x,a01.y,a23.x,a23.y,a45.x,a45.y,a67.x,a67.y};
            #pragma unroll
            for (int i=0;i<8;i++)
                #pragma unroll
                for (int j=0;j<4;j++)
                    fma2(acc[i][j], ad[i], bb[j]);
        }
        if (more){
            int q = p^1;
            Asd[q][ac+0][ar]=dup2f(av.x); Asd[q][ac+1][ar]=dup2f(av.y);
            Asd[q][ac+2][ar]=dup2f(av.z); Asd[q][ac+3][ar]=dup2f(av.w);
            *(float4*)&Bs[q][br][bc] = bv;
        }
        __syncthreads();
        p ^= 1;
    }

    int gn0 = n0 + tx*8;
    if (gn0 >= N) return;
    #pragma unroll
    for (int i=0;i<8;i++){
        int gm = m0 + ty*8 + i;
        if (gm >= M) continue;
        float bvl = (flags & 8) ? 0.f : bias[gm];
        float r[8];
        #pragma unroll
        for (int j=0;j<4;j++){
            float2 c = up2(acc[i][j]);
            r[2*j]   = c.x + bvl;
            r[2*j+1] = c.y + bvl;
        }
        if (flags & 1){
            #pragma unroll
            for (int j=0;j<8;j++) r[j] = gelu_tanh(r[j]);
        }
        size_t off = (size_t)gm*N + gn0;
        if (flags & 2){
            float4 p0 = *(const float4*)&addp[(size_t)b*M*N + off];
            float4 p1 = *(const float4*)&addp[(size_t)b*M*N + off + 4];
            r[0]+=p0.x; r[1]+=p0.y; r[2]+=p0.z; r[3]+=p0.w;
            r[4]+=p1.x; r[5]+=p1.y; r[6]+=p1.z; r[7]+=p1.w;
        }
        if (flags & 4){
            float4 p0 = *(const float4*)&addp[off];
            float4 p1 = *(const float4*)&addp[off + 4];
            r[0]+=p0.x; r[1]+=p0.y; r[2]+=p0.z; r[3]+=p0.w;
            r[4]+=p1.x; r[5]+=p1.y; r[6]+=p1.z; r[7]+=p1.w;
        }
        *(float4*)&Cp[off]     = make_float4(r[0],r[1],r[2],r[3]);
        *(float4*)&Cp[off + 4] = make_float4(r[4],r[5],r[6],r[7]);
    }
}

// ---------------- Legendre: out[bc,t,m] = sum_j w[m,j,t]*in[bc,j,m]  (paired j) ----------
__global__ __launch_bounds__(128) void k_legendre(const float2* __restrict__ in,
                                                  float2* __restrict__ out,
                                                  const float* __restrict__ w){
    __shared__ __align__(16) float2 s[8][4][128];
    int bc0 = blockIdx.x*8, m0 = blockIdx.y*4, t = threadIdx.x;
    #pragma unroll
    for (int q=0;q<8;q++){
        int lin = t + q*128;
        int j = lin & 127, r = lin >> 7;
        const float4* src = (const float4*)&in[((size_t)(bc0+r)*NLAT + j)*MP + m0];
        float4 v0 = src[0], v1 = src[1];
        s[r][0][j] = make_float2(v0.x,v0.y);
        s[r][1][j] = make_float2(v0.z,v0.w);
        s[r][2][j] = make_float2(v1.x,v1.y);
        s[r][3][j] = make_float2(v1.z,v1.w);
    }
    __syncthreads();
    u64 acc[8][4];
    #pragma unroll
    for (int r=0;r<8;r++)
        #pragma unroll
        for (int m4=0;m4<4;m4++) acc[r][m4]=0ull;
    #pragma unroll 2
    for (int jp=0;jp<NLAT/2;jp++){
        u64 w0[4], w1[4];
        #pragma unroll
        for (int m4=0;m4<4;m4++){
            const float* wp = &w[((size_t)(m0+m4)*NLAT + 2*jp)*NLAT + t];
            w0[m4] = dup2f(wp[0]);
            w1[m4] = dup2f(wp[NLAT]);
        }
        #pragma unroll
        for (int r=0;r<8;r++)
            #pragma unroll
            for (int m4=0;m4<4;m4++){
                ulonglong2 v = *(const ulonglong2*)&s[r][m4][2*jp];
                fma2(acc[r][m4], v.x, w0[m4]);
                fma2(acc[r][m4], v.y, w1[m4]);
            }
    }
    #pragma unroll
    for (int r=0;r<8;r++){
        float2 c0 = up2(acc[r][0]), c1 = up2(acc[r][1]);
        float2 c2 = up2(acc[r][2]), c3 = up2(acc[r][3]);
        float4* dst = (float4*)&out[((size_t)(bc0+r)*NLAT + t)*MP + m0];
        dst[0] = make_float4(c0.x,c0.y,c1.x,c1.y);
        dst[1] = make_float4(c2.x,c2.y,c3.x,c3.y);
    }
}

// ---------------- dhconv: out[b,o,l,m] = sum_i in[b,i,l,m] * W[l,i,o] (complex) ----------
__global__ __launch_bounds__(256) void k_dhconv(const float2* __restrict__ in,
                                                float2* __restrict__ out,
                                                const float2* __restrict__ w){
    __shared__ float2 Av[2][16][32];
    __shared__ float2 Wa[16][64];
    __shared__ float2 Wb[16][64];
    int m0 = blockIdx.x*32, l = blockIdx.y, o0 = blockIdx.z*64;
    int t = threadIdx.x, mm = t & 31, og = t >> 5;
    int m = m0 + mm;
    bool mok = (m < MP);
    u64 acc[2][8];
    #pragma unroll
    for (int b2=0;b2<2;b2++)
        #pragma unroll
        for (int j=0;j<8;j++) acc[b2][j]=0ull;

    for (int i0=0;i0<EMB;i0+=16){
        #pragma unroll
        for (int q=0;q<4;q++){
            int lin = t + q*256;
            int amm = lin & 31, aii = (lin >> 5) & 15, ab = lin >> 9;
            int am = m0 + amm;
            float2 v = make_float2(0.f,0.f);
            if (am < MP)
                v = in[((size_t)(ab*EMB + i0+aii)*NLAT + l)*MP + am];
            Av[ab][aii][amm] = v;
        }
        #pragma unroll
        for (int q=0;q<4;q++){
            int lin = t + q*256;
            int oo = lin & 63, wii = lin >> 6;
            float2 wv = w[((size_t)l*EMB + i0+wii)*EMB + o0 + oo];
            Wa[wii][oo] = wv;
            Wb[wii][oo] = make_float2(-wv.y, wv.x);
        }
        __syncthreads();
        #pragma unroll
        for (int ii=0;ii<16;ii++){
            ulonglong2 wa0 = *(ulonglong2*)&Wa[ii][og*8+0];
            ulonglong2 wa1 = *(ulonglong2*)&Wa[ii][og*8+2];
            ulonglong2 wa2 = *(ulonglong2*)&Wa[ii][og*8+4];
            ulonglong2 wa3 = *(ulonglong2*)&Wa[ii][og*8+6];
            ulonglong2 wb0 = *(ulonglong2*)&Wb[ii][og*8+0];
            ulonglong2 wb1 = *(ulonglong2*)&Wb[ii][og*8+2];
            ulonglong2 wb2 = *(ulonglong2*)&Wb[ii][og*8+4];
            ulonglong2 wb3 = *(ulonglong2*)&Wb[ii][og*8+6];
            u64 wav[8] = {wa0.x,wa0.y,wa1.x,wa1.y,wa2.x,wa2.y,wa3.x,wa3.y};
            u64 wbv[8] = {wb0.x,wb0.y,wb1.x,wb1.y,wb2.x,wb2.y,wb3.x,wb3.y};
            #pragma unroll
            for (int b2=0;b2<2;b2++){
                float2 a = Av[b2][ii][mm];
                u64 ax = dup2f(a.x), ay = dup2f(a.y);
                #pragma unroll
                for (int j=0;j<8;j++){
                    fma2(acc[b2][j], ax, wav[j]);
                    fma2(acc[b2][j], ay, wbv[j]);
                }
            }
        }
        __syncthreads();
    }
    if (mok){
        #pragma unroll
        for (int b2=0;b2<2;b2++)
            #pragma unroll
            for (int j=0;j<8;j++)
                out[((size_t)(b2*EMB + o0 + og*8 + j)*NLAT + l)*MP + m] = up2(acc[b2][j]);
    }
}

// ---------------- launcher ----------------
extern "C" void kernel_launch(void* const* d_in, const int* in_sizes, int n_in,
                              void* d_out, int out_size){
    const float* x       = (const float*)d_in[0];
    const float* w_enc   = (const float*)d_in[1];
    const float* b_enc   = (const float*)d_in[2];
    const float* pos     = (const float*)d_in[3];
    const float* spec_w  = (const float*)d_in[4];
    const float* w1      = (const float*)d_in[5];
    const float* b1      = (const float*)d_in[6];
    const float* w2      = (const float*)d_in[7];
    const float* b2      = (const float*)d_in[8];
    const float* w_dec   = (const float*)d_in[9];
    const float* b_dec   = (const float*)d_in[10];
    const float* sht_wt  = (const float*)d_in[11];
    const float* isht_wt = (const float*)d_in[12];
    float* out = (float*)d_out;

    float *ph, *pt, *pwtT, *piwt, *pTf, *pTi;
    float2 *pA, *pB, *pw;
    cudaGetSymbolAddress((void**)&ph,   g_h);
    cudaGetSymbolAddress((void**)&pt,   g_t);
    cudaGetSymbolAddress((void**)&pA,   g_A);
    cudaGetSymbolAddress((void**)&pB,   g_B);
    cudaGetSymbolAddress((void**)&pw,   g_w);
    cudaGetSymbolAddress((void**)&pwtT, g_wtT);
    cudaGetSymbolAddress((void**)&piwt, g_iwt);
    cudaGetSymbolAddress((void**)&pTf,  g_Tf);
    cudaGetSymbolAddress((void**)&pTi,  g_Ti);

    k_init_tables<<<(NLON*MI + 255)/256, 256>>>();
    k_prep_wt<<<(MP*NLAT*NLAT + 255)/256, 256>>>(sht_wt, isht_wt);
    {
        dim3 g(NLAY*EMB, EMB/32, NLAT/32);
        k_pack_w<<<g, 256>>>((const float2*)spec_w);
    }

    // encoder: h = W_enc x + b_enc + pos
    {
        dim3 g(PSP/128, 2, NB);
        k_sgemm<<<g, 256>>>(w_enc, x, ph, b_enc, pos, EMB, PSP, CINC, 4);
    }

    for (int l=0;l<NLAY;l++){
        {   // forward rFFT as GEMM: g_A[row][mi] = sum_n h[row][n] * Tf[n][mi]
            dim3 g((MI+127)/128, ROWS/128, 1);
            k_sgemm<<<g, 256>>>(ph, pTf, (float*)pA, nullptr, nullptr, ROWS, MI, NLON, 8);
        }
        {
            dim3 g(NB*EMB/8, MP/4);
            k_legendre<<<g, 128>>>(pA, pB, pwtT);
        }
        {
            dim3 g(5, NLAT, 4);
            k_dhconv<<<g, 256>>>(pB, pA, pw + (size_t)l*NLAT*EMB*EMB);
        }
        {
            dim3 g(NB*EMB/8, MP/4);
            k_legendre<<<g, 128>>>(pA, pB, piwt);
        }
        {   // inverse rFFT as GEMM + gelu + residual: h = gelu(B*Ti) + h
            dim3 g(NLON/128, ROWS/128, 1);
            k_sgemm<<<g, 256>>>((const float*)pB, pTi, ph, nullptr, ph, ROWS, NLON, MI, 8|1|2);
        }

        {   // MLP1: t = gelu(W1 h + b1)
            dim3 g(PSP/128, HID/128, NB);
            k_sgemm<<<g, 256>>>(w1 + (size_t)l*HID*EMB, ph, pt,
                                b1 + (size_t)l*HID, nullptr, HID, PSP, EMB, 1);
        }
        {   // MLP2: h = W2 t + b2 + h
            dim3 g(PSP/128, EMB/128, NB);
            k_sgemm<<<g, 256>>>(w2 + (size_t)l*EMB*HID, pt, ph,
                                b2 + (size_t)l*EMB, ph, EMB, PSP, HID, 2);
        }
    }

    // decoder
    {
        dim3 g(PSP/128, 1, NB);
        k_sgemm<<<g, 256>>>(w_dec, ph, out, b_dec, nullptr, COUTC, PSP, EMB, 0);
    }
}

// round 4
// speedup vs baseline: 1.0071x; 1.0071x over previous
#include <cuda_runtime.h>
#include <math.h>

typedef unsigned long long u64;

// ---------------- problem constants ----------------
#define NB     2
#define CINC   8
#define COUTC  8
#define NLAT   128
#define NLON   256
#define EMB    256
#define HID    512
#define NLAY   4
#define MM     129
#define MP     132                      // padded mmax (multiple of 4)
#define MI     264                      // interleaved spectral width = 2*MP
#define PSP    (NLAT*NLON)              // 32768
#define ROWS   (NB*EMB*NLAT)            // 65536

// ---------------- scratch ----------------
__device__ float2 g_A[(size_t)ROWS*MP];            // spectral buf A  [row][m132] interleaved
__device__ float2 g_B[(size_t)ROWS*MP];            // spectral buf B
__device__ float  g_h [(size_t)NB*EMB*PSP];
__device__ float  g_t [(size_t)NB*HID*PSP];
__device__ float  g_wtT[(size_t)MP*NLAT*NLAT];     // sht_wt  -> [m][k][l], zero-padded m
__device__ float  g_iwt[(size_t)MP*NLAT*NLAT];     // isht_wt -> [m][l][k], zero-padded m
__device__ float2 g_w[(size_t)NLAY*NLAT*EMB*EMB];  // spec_w  -> [lay][l][i][o] complex
__device__ float  g_Tf[(size_t)NLON*MI + 256];     // fwd DFT table [n][mi], row stride MI
__device__ float  g_Ti[(size_t)MI*NLON + 256];     // inv DFT table [mi][n]

// ---------------- f32x2 helpers ----------------
__device__ __forceinline__ u64 pk2(float lo, float hi){
    u64 r; asm("mov.b64 %0,{%1,%2};" : "=l"(r) : "f"(lo), "f"(hi)); return r;
}
__device__ __forceinline__ u64 dup2f(float v){ return pk2(v, v); }
__device__ __forceinline__ void fma2(u64 &d, u64 a, u64 b){
    asm("fma.rn.f32x2 %0,%1,%2,%0;" : "+l"(d) : "l"(a), "l"(b));
}
__device__ __forceinline__ float2 up2(u64 v){
    float x, y; asm("mov.b64 {%0,%1},%2;" : "=f"(x), "=f"(y) : "l"(v));
    return make_float2(x, y);
}
__device__ __forceinline__ float gelu_tanh(float x){
    float x3 = x*x*x;
    return 0.5f*x*(1.0f + tanhf(0.79788456080286535588f*(x + 0.044715f*x3)));
}

// ---------------- tables ----------------
__global__ void k_init_tables(){
    int i = blockIdx.x*blockDim.x + threadIdx.x;
    if (i >= NLON*MI) return;
    const double PI_D = 3.141592653589793238462643383279502884;
    {   // forward: Tf[n][mi], mi = 2m+c;  value = (2pi/256) * e^{-i 2pi n m /256}
        int n = i / MI, mi = i % MI, m = mi >> 1, c = mi & 1;
        float v = 0.f;
        if (m < MM){
            double ang = -2.0*PI_D*(double)((n*m)&255)/256.0;
            double sc  =  2.0*PI_D/256.0;
            v = (float)((c ? sin(ang) : cos(ang))*sc);
        }
        g_Tf[i] = v;
    }
    {   // inverse: Ti[mi][n]
        int mi = i / NLON, n = i % NLON, m = mi >> 1, c = mi & 1;
        float v = 0.f;
        if (m < MM){
            double a2 = 2.0*PI_D*(double)((n*m)&255)/256.0;
            if (m==0 || m==128) v = c ? 0.f : (float)cos(a2);
            else                v = c ? (float)(-2.0*sin(a2)) : (float)(2.0*cos(a2));
        }
        g_Ti[i] = v;
    }
}

// sht_wt[m][l][k] -> g_wtT[m][k][l] ; isht_wt[m][l][k] -> g_iwt[m][l][k]; pad m to 132 w/ zeros
__global__ void k_prep_wt(const float* __restrict__ sht, const float* __restrict__ isht){
    int i = blockIdx.x*blockDim.x + threadIdx.x;
    if (i >= MP*NLAT*NLAT) return;
    int t = i & 127;
    int j = (i >> 7) & 127;
    int m = i >> 14;
    float v1 = 0.f, v2 = 0.f;
    if (m < MM){
        v1 = sht [((size_t)m*NLAT + t)*NLAT + j];   // out[m][k=j][l=t]
        v2 = isht[((size_t)m*NLAT + j)*NLAT + t];   // out[m][l=j][k=t]
    }
    g_wtT[i] = v1;
    g_iwt[i] = v2;
}

// spec_w [lay][i][o][l]{re,im} -> g_w [lay][l][i][o] float2 (smem-tiled transpose)
__global__ __launch_bounds__(256) void k_pack_w(const float2* __restrict__ sw){
    __shared__ float2 tile[32][33];
    int li = blockIdx.x;                 // lay*256 + i
    int o0 = blockIdx.y*32, l0 = blockIdx.z*32;
    int oo = threadIdx.x >> 5, ll = threadIdx.x & 31;
    #pragma unroll
    for (int p=0;p<4;p++){
        int o = oo + p*8;
        tile[o][ll] = sw[((size_t)li*EMB + o0 + o)*NLAT + l0 + ll];
    }
    __syncthreads();
    int lay = li >> 8, ii = li & 255;
    #pragma unroll
    for (int p=0;p<4;p++){
        int l = oo + p*8;
        g_w[(((size_t)lay*NLAT + l0 + l)*EMB + ii)*EMB + o0 + ll] = tile[ll][l];
    }
}

// ---------------- SGEMM: C[b,m,n] = sum_k A[m,k]*B[b,k,n]  (128x128, FFMA2, dbuf) ------
// flags: 1 = gelu, 2 = add addp[b,m,n], 4 = add addp[m,n], 8 = no bias
__global__ __launch_bounds__(256) void k_sgemm(
    const float* __restrict__ A, const float* __restrict__ Bmat,
    float* C, const float* __restrict__ bias, const float* __restrict__ addp,
    int M, int N, int K, int flags)
{
    __shared__ u64   Asd[2][8][128];
    __shared__ float Bs [2][8][128];
    int b = blockIdx.z;
    const float* Bp = Bmat + (size_t)b*K*N;
    float* Cp       = C    + (size_t)b*M*N;
    int m0 = blockIdx.y*128, n0 = blockIdx.x*128;
    int tid = threadIdx.x, tx = tid & 15, ty = tid >> 4;
    int ar = tid >> 1,  ac = (tid & 1)*4;
    int br = tid >> 5,  bc = (tid & 31)*4;

    // preload tile 0
    float4 av = make_float4(0.f,0.f,0.f,0.f);
    if (m0+ar < M) av = *(const float4*)&A[(size_t)(m0+ar)*K + ac];
    float4 bv = *(const float4*)&Bp[(size_t)br*N + n0 + bc];
    Asd[0][ac+0][ar]=dup2f(av.x); Asd[0][ac+1][ar]=dup2f(av.y);
    Asd[0][ac+2][ar]=dup2f(av.z); Asd[0][ac+3][ar]=dup2f(av.w);
    *(float4*)&Bs[0][br][bc] = bv;
    __syncthreads();

    u64 acc[8][4];
    #pragma unroll
    for (int i=0;i<8;i++)
        #pragma unroll
        for (int j=0;j<4;j++) acc[i][j]=0ull;

    int p = 0;
    for (int k0=0;k0<K;k0+=8){
        int k1 = k0 + 8;
        bool more = (k1 < K);
        if (more){
            av = make_float4(0.f,0.f,0.f,0.f);
            if (m0+ar < M) av = *(const float4*)&A[(size_t)(m0+ar)*K + k1 + ac];
            bv = *(const float4*)&Bp[(size_t)(k1+br)*N + n0 + bc];
        }
        #pragma unroll
        for (int kk=0;kk<8;kk++){
            ulonglong2 a01 = *(ulonglong2*)&Asd[p][kk][ty*8+0];
            ulonglong2 a23 = *(ulonglong2*)&Asd[p][kk][ty*8+2];
            ulonglong2 a45 = *(ulonglong2*)&Asd[p][kk][ty*8+4];
            ulonglong2 a67 = *(ulonglong2*)&Asd[p][kk][ty*8+6];
            float4 b03 = *(float4*)&Bs[p][kk][tx*8];
            float4 b47 = *(float4*)&Bs[p][kk][tx*8+4];
            u64 bb[4] = {pk2(b03.x,b03.y), pk2(b03.z,b03.w),
                         pk2(b47.x,b47.y), pk2(b47.z,b47.w)};
            u64 ad[8] = {a01.x,a01.y,a23.x,a23.y,a45.x,a45.y,a67.x,a67.y};
            #pragma unroll
            for (int i=0;i<8;i++)
                #pragma unroll
                for (int j=0;j<4;j++)
                    fma2(acc[i][j], ad[i], bb[j]);
        }
        if (more){
            int q = p^1;
            Asd[q][ac+0][ar]=dup2f(av.x); Asd[q][ac+1][ar]=dup2f(av.y);
            Asd[q][ac+2][ar]=dup2f(av.z); Asd[q][ac+3][ar]=dup2f(av.w);
            *(float4*)&Bs[q][br][bc] = bv;
        }
        __syncthreads();
        p ^= 1;
    }

    int gn0 = n0 + tx*8;
    if (gn0 >= N) return;
    #pragma unroll
    for (int i=0;i<8;i++){
        int gm = m0 + ty*8 + i;
        if (gm >= M) continue;
        float bvl = (flags & 8) ? 0.f : bias[gm];
        float r[8];
        #pragma unroll
        for (int j=0;j<4;j++){
            float2 c = up2(acc[i][j]);
            r[2*j]   = c.x + bvl;
            r[2*j+1] = c.y + bvl;
        }
        if (flags & 1){
            #pragma unroll
            for (int j=0;j<8;j++) r[j] = gelu_tanh(r[j]);
        }
        size_t off = (size_t)gm*N + gn0;
        if (flags & 2){
            float4 p0 = *(const float4*)&addp[(size_t)b*M*N + off];
            float4 p1 = *(const float4*)&addp[(size_t)b*M*N + off + 4];
            r[0]+=p0.x; r[1]+=p0.y; r[2]+=p0.z; r[3]+=p0.w;
            r[4]+=p1.x; r[5]+=p1.y; r[6]+=p1.z; r[7]+=p1.w;
        }
        if (flags & 4){
            float4 p0 = *(const float4*)&addp[off];
            float4 p1 = *(const float4*)&addp[off + 4];
            r[0]+=p0.x; r[1]+=p0.y; r[2]+=p0.z; r[3]+=p0.w;
            r[4]+=p1.x; r[5]+=p1.y; r[6]+=p1.z; r[7]+=p1.w;
        }
        *(float4*)&Cp[off]     = make_float4(r[0],r[1],r[2],r[3]);
        *(float4*)&Cp[off + 4] = make_float4(r[4],r[5],r[6],r[7]);
    }
}

// ---------------- Legendre: out[bc,t,m] = sum_j w[m,j,t]*in[bc,j,m]  (paired j) ----------
__global__ __launch_bounds__(128) void k_legendre(const float2* __restrict__ in,
                                                  float2* __restrict__ out,
                                                  const float* __restrict__ w){
    __shared__ __align__(16) float2 s[8][4][128];
    int bc0 = blockIdx.x*8, m0 = blockIdx.y*4, t = threadIdx.x;
    #pragma unroll
    for (int q=0;q<8;q++){
        int lin = t + q*128;
        int j = lin & 127, r = lin >> 7;
        const float4* src = (const float4*)&in[((size_t)(bc0+r)*NLAT + j)*MP + m0];
        float4 v0 = src[0], v1 = src[1];
        s[r][0][j] = make_float2(v0.x,v0.y);
        s[r][1][j] = make_float2(v0.z,v0.w);
        s[r][2][j] = make_float2(v1.x,v1.y);
        s[r][3][j] = make_float2(v1.z,v1.w);
    }
    __syncthreads();
    u64 acc[8][4];
    #pragma unroll
    for (int r=0;r<8;r++)
        #pragma unroll
        for (int m4=0;m4<4;m4++) acc[r][m4]=0ull;
    #pragma unroll 2
    for (int jp=0;jp<NLAT/2;jp++){
        u64 w0[4], w1[4];
        #pragma unroll
        for (int m4=0;m4<4;m4++){
            const float* wp = &w[((size_t)(m0+m4)*NLAT + 2*jp)*NLAT + t];
            w0[m4] = dup2f(wp[0]);
            w1[m4] = dup2f(wp[NLAT]);
        }
        #pragma unroll
        for (int r=0;r<8;r++)
            #pragma unroll
            for (int m4=0;m4<4;m4++){
                ulonglong2 v = *(const ulonglong2*)&s[r][m4][2*jp];
                fma2(acc[r][m4], v.x, w0[m4]);
                fma2(acc[r][m4], v.y, w1[m4]);
            }
    }
    #pragma unroll
    for (int r=0;r<8;r++){
        float2 c0 = up2(acc[r][0]), c1 = up2(acc[r][1]);
        float2 c2 = up2(acc[r][2]), c3 = up2(acc[r][3]);
        float4* dst = (float4*)&out[((size_t)(bc0+r)*NLAT + t)*MP + m0];
        dst[0] = make_float4(c0.x,c0.y,c1.x,c1.y);
        dst[1] = make_float4(c2.x,c2.y,c3.x,c3.y);
    }
}

// ---------------- dhconv: out[b,o,l,m] = sum_i in[b,i,l,m] * W[l,i,o] (complex) ----------
__global__ __launch_bounds__(256) void k_dhconv(const float2* __restrict__ in,
                                                float2* __restrict__ out,
                                                const float2* __restrict__ w){
    __shared__ float2 Av[2][16][32];
    __shared__ float2 Wa[16][64];
    __shared__ float2 Wb[16][64];
    int m0 = blockIdx.x*32, l = blockIdx.y, o0 = blockIdx.z*64;
    int t = threadIdx.x, mm = t & 31, og = t >> 5;
    int m = m0 + mm;
    bool mok = (m < MP);
    u64 acc[2][8];
    #pragma unroll
    for (int b2=0;b2<2;b2++)
        #pragma unroll
        for (int j=0;j<8;j++) acc[b2][j]=0ull;

    for (int i0=0;i0<EMB;i0+=16){
        #pragma unroll
        for (int q=0;q<4;q++){
            int lin = t + q*256;
            int amm = lin & 31, aii = (lin >> 5) & 15, ab = lin >> 9;
            int am = m0 + amm;
            float2 v = make_float2(0.f,0.f);
            if (am < MP)
                v = in[((size_t)(ab*EMB + i0+aii)*NLAT + l)*MP + am];
            Av[ab][aii][amm] = v;
        }
        #pragma unroll
        for (int q=0;q<4;q++){
            int lin = t + q*256;
            int oo = lin & 63, wii = lin >> 6;
            float2 wv = w[((size_t)l*EMB + i0+wii)*EMB + o0 + oo];
            Wa[wii][oo] = wv;
            Wb[wii][oo] = make_float2(-wv.y, wv.x);
        }
        __syncthreads();
        #pragma unroll
        for (int ii=0;ii<16;ii++){
            ulonglong2 wa0 = *(ulonglong2*)&Wa[ii][og*8+0];
            ulonglong2 wa1 = *(ulonglong2*)&Wa[ii][og*8+2];
            ulonglong2 wa2 = *(ulonglong2*)&Wa[ii][og*8+4];
            ulonglong2 wa3 = *(ulonglong2*)&Wa[ii][og*8+6];
            ulonglong2 wb0 = *(ulonglong2*)&Wb[ii][og*8+0];
            ulonglong2 wb1 = *(ulonglong2*)&Wb[ii][og*8+2];
            ulonglong2 wb2 = *(ulonglong2*)&Wb[ii][og*8+4];
            ulonglong2 wb3 = *(ulonglong2*)&Wb[ii][og*8+6];
            u64 wav[8] = {wa0.x,wa0.y,wa1.x,wa1.y,wa2.x,wa2.y,wa3.x,wa3.y};
            u64 wbv[8] = {wb0.x,wb0.y,wb1.x,wb1.y,wb2.x,wb2.y,wb3.x,wb3.y};
            #pragma unroll
            for (int b2=0;b2<2;b2++){
                float2 a = Av[b2][ii][mm];
                u64 ax = dup2f(a.x), ay = dup2f(a.y);
                #pragma unroll
                for (int j=0;j<8;j++){
                    fma2(acc[b2][j], ax, wav[j]);
                    fma2(acc[b2][j], ay, wbv[j]);
                }
            }
        }
        __syncthreads();
    }
    if (mok){
        #pragma unroll
        for (int b2=0;b2<2;b2++)
            #pragma unroll
            for (int j=0;j<8;j++)
                out[((size_t)(b2*EMB + o0 + og*8 + j)*NLAT + l)*MP + m] = up2(acc[b2][j]);
    }
}

// ---------------- launcher ----------------
extern "C" void kernel_launch(void* const* d_in, const int* in_sizes, int n_in,
                              void* d_out, int out_size){
    const float* x       = (const float*)d_in[0];
    const float* w_enc   = (const float*)d_in[1];
    const float* b_enc   = (const float*)d_in[2];
    const float* pos     = (const float*)d_in[3];
    const float* spec_w  = (const float*)d_in[4];
    const float* w1      = (const float*)d_in[5];
    const float* b1      = (const float*)d_in[6];
    const float* w2      = (const float*)d_in[7];
    const float* b2      = (const float*)d_in[8];
    const float* w_dec   = (const float*)d_in[9];
    const float* b_dec   = (const float*)d_in[10];
    const float* sht_wt  = (const float*)d_in[11];
    const float* isht_wt = (const float*)d_in[12];
    float* out = (float*)d_out;

    float *ph, *pt, *pwtT, *piwt, *pTf, *pTi;
    float2 *pA, *pB, *pw;
    cudaGetSymbolAddress((void**)&ph,   g_h);
    cudaGetSymbolAddress((void**)&pt,   g_t);
    cudaGetSymbolAddress((void**)&pA,   g_A);
    cudaGetSymbolAddress((void**)&pB,   g_B);
    cudaGetSymbolAddress((void**)&pw,   g_w);
    cudaGetSymbolAddress((void**)&pwtT, g_wtT);
    cudaGetSymbolAddress((void**)&piwt, g_iwt);
    cudaGetSymbolAddress((void**)&pTf,  g_Tf);
    cudaGetSymbolAddress((void**)&pTi,  g_Ti);

    k_init_tables<<<(NLON*MI + 255)/256, 256>>>();
    k_prep_wt<<<(MP*NLAT*NLAT + 255)/256, 256>>>(sht_wt, isht_wt);
    {
        dim3 g(NLAY*EMB, EMB/32, NLAT/32);
        k_pack_w<<<g, 256>>>((const float2*)spec_w);
    }

    // encoder: h = W_enc x + b_enc + pos
    {
        dim3 g(PSP/128, 2, NB);
        k_sgemm<<<g, 256>>>(w_enc, x, ph, b_enc, pos, EMB, PSP, CINC, 4);
    }

    for (int l=0;l<NLAY;l++){
        {   // forward rFFT as GEMM: g_A[row][mi] = sum_n h[row][n] * Tf[n][mi]
            dim3 g((MI+127)/128, ROWS/128, 1);
            k_sgemm<<<g, 256>>>(ph, pTf, (float*)pA, nullptr, nullptr, ROWS, MI, NLON, 8);
        }
        {
            dim3 g(NB*EMB/8, MP/4);
            k_legendre<<<g, 128>>>(pA, pB, pwtT);
        }
        {
            dim3 g(5, NLAT, 4);
            k_dhconv<<<g, 256>>>(pB, pA, pw + (size_t)l*NLAT*EMB*EMB);
        }
        {
            dim3 g(NB*EMB/8, MP/4);
            k_legendre<<<g, 128>>>(pA, pB, piwt);
        }
        {   // inverse rFFT as GEMM + gelu + residual: h = gelu(B*Ti) + h
            dim3 g(NLON/128, ROWS/128, 1);
            k_sgemm<<<g, 256>>>((const float*)pB, pTi, ph, nullptr, ph, ROWS, NLON, MI, 8|1|2);
        }

        {   // MLP1: t = gelu(W1 h + b1)
            dim3 g(PSP/128, HID/128, NB);
            k_sgemm<<<g, 256>>>(w1 + (size_t)l*HID*EMB, ph, pt,
                                b1 + (size_t)l*HID, nullptr, HID, PSP, EMB, 1);
        }
        {   // MLP2: h = W2 t + b2 + h
            dim3 g(PSP/128, EMB/128, NB);
            k_sgemm<<<g, 256>>>(w2 + (size_t)l*EMB*HID, pt, ph,
                                b2 + (size_t)l*EMB, ph, EMB, PSP, HID, 2);
        }
    }

    // decoder
    {
        dim3 g(PSP/128, 1, NB);
        k_sgemm<<<g, 256>>>(w_dec, ph, out, b_dec, nullptr, COUTC, PSP, EMB, 0);
    }
}